// round 8
// baseline (speedup 1.0000x reference)
#include <cuda_runtime.h>
#include <cuda_fp16.h>
#include <cuda_fp8.h>
#include <cstdint>

// ---------------------------------------------------------------- shapes
#define D_FEAT 4096
#define N_SAMP 8192
#define OUT_D  2048

// ---------------------------------------------------------------- scratch
__device__ __half         g_psi_h16[(size_t)OUT_D * N_SAMP];
__device__ unsigned char  g_psi_h8 [(size_t)OUT_D * N_SAMP];
__device__ unsigned char  g_psi_l8 [(size_t)OUT_D * N_SAMP];
__device__ __half         g_x_h16  [(size_t)D_FEAT * N_SAMP];
__device__ unsigned char  g_x_h8   [(size_t)D_FEAT * N_SAMP];
__device__ unsigned char  g_x_l8   [(size_t)D_FEAT * N_SAMP];
__device__ __half         g_xt_h16 [(size_t)N_SAMP * D_FEAT];
__device__ unsigned char  g_xt_h8  [(size_t)N_SAMP * D_FEAT];
__device__ unsigned char  g_xt_l8  [(size_t)N_SAMP * D_FEAT];
__device__ __half         g_tmp_h16[(size_t)OUT_D * D_FEAT];
__device__ unsigned char  g_tmp_h8 [(size_t)OUT_D * D_FEAT];
__device__ unsigned char  g_tmp_l8 [(size_t)OUT_D * D_FEAT];
__device__ float g_partA[(size_t)4 * OUT_D * D_FEAT];
__device__ float g_partB[(size_t)4 * OUT_D * D_FEAT];
__device__ float g_partC[(size_t)2 * OUT_D * N_SAMP];
__device__ float g_partD[(size_t)2 * OUT_D * N_SAMP];

// ---------------------------------------------------------------- helpers
__device__ __forceinline__ uint32_t smem_u32(const void* p) {
    uint32_t a;
    asm("{ .reg .u64 t; cvta.to.shared.u64 t, %1; cvt.u32.u64 %0, t; }" : "=r"(a) : "l"(p));
    return a;
}
__device__ __forceinline__ void cpasync16(uint32_t s, const void* g) {
    asm volatile("cp.async.cg.shared.global [%0], [%1], 16;" :: "r"(s), "l"(g));
}
__device__ __forceinline__ void cp_commit() {
    asm volatile("cp.async.commit_group;" ::: "memory");
}
__device__ __forceinline__ void cp_wait1() {
    asm volatile("cp.async.wait_group 1;" ::: "memory");
}
__device__ __forceinline__ void ldsm4(uint32_t* r, uint32_t addr) {
    asm volatile("ldmatrix.sync.aligned.m8n8.x4.shared.b16 {%0,%1,%2,%3}, [%4];"
                 : "=r"(r[0]), "=r"(r[1]), "=r"(r[2]), "=r"(r[3]) : "r"(addr));
}
__device__ __forceinline__ void mma_f16(float* c, const uint32_t* a, const uint32_t* b) {
    asm volatile("mma.sync.aligned.m16n8k16.row.col.f32.f16.f16.f32 "
                 "{%0,%1,%2,%3}, {%4,%5,%6,%7}, {%8,%9}, {%0,%1,%2,%3};"
                 : "+f"(c[0]), "+f"(c[1]), "+f"(c[2]), "+f"(c[3])
                 : "r"(a[0]), "r"(a[1]), "r"(a[2]), "r"(a[3]), "r"(b[0]), "r"(b[1]));
}
__device__ __forceinline__ void mma_e4m3(float* c, const uint32_t* a, const uint32_t* b) {
    asm volatile("mma.sync.aligned.m16n8k32.row.col.f32.e4m3.e4m3.f32 "
                 "{%0,%1,%2,%3}, {%4,%5,%6,%7}, {%8,%9}, {%0,%1,%2,%3};"
                 : "+f"(c[0]), "+f"(c[1]), "+f"(c[2]), "+f"(c[3])
                 : "r"(a[0]), "r"(a[1]), "r"(a[2]), "r"(a[3]), "r"(b[0]), "r"(b[1]));
}
__device__ __forceinline__ uint32_t sw128(uint32_t off) {
    return off ^ ((off >> 3) & 0x70);
}
__device__ __forceinline__ unsigned char cvt_e4m3(float v) {
    return (unsigned char)__nv_cvt_float_to_fp8(v, __NV_SATFINITE, __NV_E4M3);
}
__device__ __forceinline__ uint32_t pack4_e4m3(float a, float b, float c, float d) {
    uint32_t lo = (uint32_t)__nv_cvt_float2_to_fp8x2(make_float2(a, b), __NV_SATFINITE, __NV_E4M3);
    uint32_t hi = (uint32_t)__nv_cvt_float2_to_fp8x2(make_float2(c, d), __NV_SATFINITE, __NV_E4M3);
    return lo | (hi << 16);
}

// ---------------------------------------------------- Psi: mean+center+split
__global__ void prep_psi_kernel(const float* __restrict__ Psi,
                                __half* __restrict__ h16,
                                unsigned char* __restrict__ h8,
                                unsigned char* __restrict__ l8) {
    const int row = blockIdx.x;
    const float4* p = reinterpret_cast<const float4*>(Psi) + (size_t)row * (N_SAMP / 4);
    float4 v[8];
    float s = 0.f;
    #pragma unroll
    for (int q = 0; q < 8; ++q) {
        v[q] = p[q * 256 + threadIdx.x];
        s += (v[q].x + v[q].y) + (v[q].z + v[q].w);
    }
    __shared__ float red[256];
    red[threadIdx.x] = s;
    __syncthreads();
    #pragma unroll
    for (int off = 128; off > 0; off >>= 1) {
        if (threadIdx.x < off) red[threadIdx.x] += red[threadIdx.x + off];
        __syncthreads();
    }
    const float m = red[0] * (1.0f / N_SAMP);
    ushort4* hp = reinterpret_cast<ushort4*>(h16) + (size_t)row * (N_SAMP / 4);
    uint32_t* h8p = reinterpret_cast<uint32_t*>(h8) + (size_t)row * (N_SAMP / 4);
    uint32_t* l8p = reinterpret_cast<uint32_t*>(l8) + (size_t)row * (N_SAMP / 4);
    #pragma unroll
    for (int q = 0; q < 8; ++q) {
        float w0 = v[q].x - m, w1 = v[q].y - m, w2 = v[q].z - m, w3 = v[q].w - m;
        __half a0 = __float2half_rn(w0), a1 = __float2half_rn(w1);
        __half a2 = __float2half_rn(w2), a3 = __float2half_rn(w3);
        float f0 = __half2float(a0), f1 = __half2float(a1);
        float f2 = __half2float(a2), f3 = __half2float(a3);
        const size_t idx = q * 256 + threadIdx.x;
        hp[idx] = make_ushort4(__half_as_ushort(a0), __half_as_ushort(a1),
                               __half_as_ushort(a2), __half_as_ushort(a3));
        h8p[idx] = pack4_e4m3(f0, f1, f2, f3);
        l8p[idx] = pack4_e4m3((w0 - f0) * 2048.f, (w1 - f1) * 2048.f,
                              (w2 - f2) * 2048.f, (w3 - f3) * 2048.f);
    }
}

// ---------------------------------------------------- x: split both layouts
__global__ void prep_x_kernel(const float* __restrict__ x,
                              __half* __restrict__ xh, unsigned char* __restrict__ xh8,
                              unsigned char* __restrict__ xl8,
                              __half* __restrict__ xth, unsigned char* __restrict__ xth8,
                              unsigned char* __restrict__ xtl8) {
    __shared__ float tile[32][33];
    const int n0 = blockIdx.x * 32;
    const int d0 = blockIdx.y * 32;
    const int tx = threadIdx.x, ty = threadIdx.y;   // 32 x 8
    #pragma unroll
    for (int k = 0; k < 4; ++k) {
        const int d = d0 + ty + 8 * k;
        const size_t o = (size_t)d * N_SAMP + n0 + tx;
        float v = x[o];
        tile[ty + 8 * k][tx] = v;
        __half h = __float2half_rn(v);
        float hf = __half2float(h);
        xh[o]  = h;
        xh8[o] = cvt_e4m3(hf);
        xl8[o] = cvt_e4m3((v - hf) * 2048.f);
    }
    __syncthreads();
    #pragma unroll
    for (int k = 0; k < 4; ++k) {
        float v = tile[tx][ty + 8 * k];
        __half h = __float2half_rn(v);
        float hf = __half2float(h);
        const size_t o = (size_t)(n0 + ty + 8 * k) * D_FEAT + d0 + tx;
        xth[o]  = h;
        xth8[o] = cvt_e4m3(hf);
        xtl8[o] = cvt_e4m3((v - hf) * 2048.f);
    }
}

// ---------------------------------------------------------------- fp16 h*h GEMM
// Cpart[z][M,N] = Ah16[M,kz:kz+klen] * Bh16[N,kz:kz+klen]^T (NT, split-K)
// CTA 128x128, 256 thr, warp tile 32x64, K_TILE=64, 3-stage ring (96KB), 2 CTAs/SM.
#define STG_BYTES 32768

__global__ void __launch_bounds__(256, 2)
gemm_hh(const __half* __restrict__ A, const __half* __restrict__ B,
        float* __restrict__ Cpart, int N, int K, int klen) {
    extern __shared__ char smem[];
    const uint32_t sb = smem_u32(smem);
    const int tid = threadIdx.x, wid = tid >> 5, lane = tid & 31;
    const int wm = wid & 3, wn = wid >> 2;
    const int m0 = blockIdx.x * 128, n0 = blockIdx.y * 128;
    const int kz = blockIdx.z * klen;
    float* C = Cpart + (size_t)blockIdx.z * ((size_t)gridDim.x * 128) * N;

    // loader: [128 rows][128B] per array; 4 chunks/thread/array
    uint32_t soff[4];
    const __half *pA[4], *pB[4];
    #pragma unroll
    for (int q = 0; q < 4; ++q) {
        const int id = q * 256 + tid;
        const int r = id >> 3, c = id & 7;
        soff[q] = sw128((uint32_t)(r * 128 + c * 16));
        pA[q] = A + (size_t)(m0 + r) * K + kz + c * 8;
        pB[q] = B + (size_t)(n0 + r) * K + kz + c * 8;
    }
    auto load_stage = [&](int t) {
        const uint32_t base = sb + (t % 3) * STG_BYTES;
        #pragma unroll
        for (int q = 0; q < 4; ++q) {
            cpasync16(base + soff[q], pA[q]);
            cpasync16(base + 16384 + soff[q], pB[q]);
            pA[q] += 64; pB[q] += 64;
        }
        cp_commit();
    };

    const int quad = lane >> 3, l8r = lane & 7;
    uint32_t aoff0[2], boff0[4];
    #pragma unroll
    for (int i = 0; i < 2; ++i)
        aoff0[i] = sw128((uint32_t)((wm * 32 + (quad & 1) * 8 + l8r + i * 16) * 128 + (quad >> 1) * 16));
    #pragma unroll
    for (int jt = 0; jt < 4; ++jt)
        boff0[jt] = sw128((uint32_t)((wn * 64 + (quad >> 1) * 8 + l8r + jt * 16) * 128 + (quad & 1) * 16));

    float acc[2][8][4];
    #pragma unroll
    for (int i = 0; i < 2; ++i)
        #pragma unroll
        for (int j = 0; j < 8; ++j)
            #pragma unroll
            for (int e = 0; e < 4; ++e) acc[i][j][e] = 0.f;

    const int ntiles = klen / 64;
    load_stage(0);
    load_stage(1);

    for (int s = 0; s < ntiles; ++s) {
        cp_wait1();
        __syncthreads();
        if (s + 2 < ntiles) load_stage(s + 2);
        const uint32_t st = sb + (s % 3) * STG_BYTES;
        #pragma unroll
        for (int h = 0; h < 4; ++h) {
            const uint32_t hx = h * 32;
            uint32_t Af[2][4];
            #pragma unroll
            for (int i = 0; i < 2; ++i) ldsm4(Af[i], st + (aoff0[i] ^ hx));
            #pragma unroll
            for (int jj = 0; jj < 2; ++jj) {
                uint32_t Bf[2][4];
                #pragma unroll
                for (int j = 0; j < 2; ++j)
                    ldsm4(Bf[j], st + 16384 + (boff0[jj * 2 + j] ^ hx));
                #pragma unroll
                for (int i = 0; i < 2; ++i)
                    #pragma unroll
                    for (int j = 0; j < 4; ++j)
                        mma_f16(acc[i][jj * 4 + j], Af[i], &Bf[j >> 1][(j & 1) * 2]);
            }
        }
    }

    const int r_base = m0 + wm * 32 + (lane >> 2);
    const int c_base = n0 + wn * 64 + (lane & 3) * 2;
    #pragma unroll
    for (int i = 0; i < 2; ++i)
        #pragma unroll
        for (int j = 0; j < 8; ++j) {
            const int r0 = r_base + i * 16, c = c_base + j * 8;
            *reinterpret_cast<float2*>(C + (size_t)r0 * N + c) =
                make_float2(acc[i][j][0], acc[i][j][1]);
            *reinterpret_cast<float2*>(C + (size_t)(r0 + 8) * N + c) =
                make_float2(acc[i][j][2], acc[i][j][3]);
        }
}

// ---------------------------------------------------------------- fp8 cross GEMM
// Cpart[z][M,N] = Ah8*Bl8^T + Al8*Bh8^T over K-slab (NT, split-K).
// smem per array: [128 rows][128B] = h8 bytes 0..63 | l8 bytes 64..127. K_TILE=64.
__global__ void __launch_bounds__(256, 2)
gemm_x8(const unsigned char* __restrict__ Ah8, const unsigned char* __restrict__ Al8,
        const unsigned char* __restrict__ Bh8, const unsigned char* __restrict__ Bl8,
        float* __restrict__ Cpart, int N, int K, int klen) {
    extern __shared__ char smem[];
    const uint32_t sb = smem_u32(smem);
    const int tid = threadIdx.x, wid = tid >> 5, lane = tid & 31;
    const int wm = wid & 3, wn = wid >> 2;
    const int m0 = blockIdx.x * 128, n0 = blockIdx.y * 128;
    const int kz = blockIdx.z * klen;
    float* C = Cpart + (size_t)blockIdx.z * ((size_t)gridDim.x * 128) * N;

    uint32_t soff[4];
    const unsigned char *pA[4], *pB[4];
    #pragma unroll
    for (int q = 0; q < 4; ++q) {
        const int id = q * 256 + tid;
        const int r = id >> 3, c = id & 7;
        soff[q] = sw128((uint32_t)(r * 128 + c * 16));
        if (c < 4) {
            pA[q] = Ah8 + (size_t)(m0 + r) * K + kz + c * 16;
            pB[q] = Bh8 + (size_t)(n0 + r) * K + kz + c * 16;
        } else {
            pA[q] = Al8 + (size_t)(m0 + r) * K + kz + (c - 4) * 16;
            pB[q] = Bl8 + (size_t)(n0 + r) * K + kz + (c - 4) * 16;
        }
    }
    auto load_stage = [&](int t) {
        const uint32_t base = sb + (t % 3) * STG_BYTES;
        #pragma unroll
        for (int q = 0; q < 4; ++q) {
            cpasync16(base + soff[q], pA[q]);
            cpasync16(base + 16384 + soff[q], pB[q]);
            pA[q] += 64; pB[q] += 64;
        }
        cp_commit();
    };

    const int quad = lane >> 3, l8r = lane & 7;
    uint32_t aoff0[2], boff0[4];
    #pragma unroll
    for (int i = 0; i < 2; ++i)
        aoff0[i] = sw128((uint32_t)((wm * 32 + (quad & 1) * 8 + l8r + i * 16) * 128 + (quad >> 1) * 16));
    #pragma unroll
    for (int nb = 0; nb < 4; ++nb)
        boff0[nb] = sw128((uint32_t)((wn * 64 + (quad >> 1) * 8 + l8r + nb * 16) * 128 + (quad & 1) * 16));

    float acc[2][8][4];
    #pragma unroll
    for (int i = 0; i < 2; ++i)
        #pragma unroll
        for (int j = 0; j < 8; ++j)
            #pragma unroll
            for (int e = 0; e < 4; ++e) acc[i][j][e] = 0.f;

    const int ntiles = klen / 64;
    load_stage(0);
    load_stage(1);

    for (int s = 0; s < ntiles; ++s) {
        cp_wait1();
        __syncthreads();
        if (s + 2 < ntiles) load_stage(s + 2);
        const uint32_t st = sb + (s % 3) * STG_BYTES;
        #pragma unroll
        for (int kk = 0; kk < 2; ++kk) {
            const uint32_t kx = kk * 32;
            uint32_t Ahf[2][4], Alf[2][4];
            #pragma unroll
            for (int i = 0; i < 2; ++i) {
                ldsm4(Ahf[i], st + (aoff0[i] ^ kx));
                ldsm4(Alf[i], st + (aoff0[i] ^ (kx | 64)));
            }
            #pragma unroll
            for (int nb = 0; nb < 4; ++nb) {
                uint32_t Bhf[4], Blf[4];
                ldsm4(Bhf, st + 16384 + (boff0[nb] ^ kx));
                ldsm4(Blf, st + 16384 + (boff0[nb] ^ (kx | 64)));
                #pragma unroll
                for (int i = 0; i < 2; ++i)
                    #pragma unroll
                    for (int n8 = 0; n8 < 2; ++n8) {
                        mma_e4m3(acc[i][nb * 2 + n8], Ahf[i], &Blf[n8 * 2]);
                        mma_e4m3(acc[i][nb * 2 + n8], Alf[i], &Bhf[n8 * 2]);
                    }
            }
        }
    }

    const int r_base = m0 + wm * 32 + (lane >> 2);
    const int c_base = n0 + wn * 64 + (lane & 3) * 2;
    #pragma unroll
    for (int i = 0; i < 2; ++i)
        #pragma unroll
        for (int j = 0; j < 8; ++j) {
            const int r0 = r_base + i * 16, c = c_base + j * 8;
            *reinterpret_cast<float2*>(C + (size_t)r0 * N + c) =
                make_float2(acc[i][j][0], acc[i][j][1]);
            *reinterpret_cast<float2*>(C + (size_t)(r0 + 8) * N + c) =
                make_float2(acc[i][j][2], acc[i][j][3]);
        }
}

// ---------------------------------------------- tmp = SUM(A) + 2^-11 SUM(B); split
__global__ void reduce4_kernel(const float* __restrict__ pa, const float* __restrict__ pb,
                               __half* __restrict__ h16,
                               unsigned char* __restrict__ h8, unsigned char* __restrict__ l8) {
    const size_t i = (size_t)blockIdx.x * 256 + threadIdx.x;
    const size_t off = (size_t)OUT_D * D_FEAT / 4;
    const float4* av = reinterpret_cast<const float4*>(pa);
    const float4* bv = reinterpret_cast<const float4*>(pb);
    float4 a0 = av[i], a1 = av[i + off], a2 = av[i + 2 * off], a3 = av[i + 3 * off];
    float4 b0 = bv[i], b1 = bv[i + off], b2 = bv[i + 2 * off], b3 = bv[i + 3 * off];
    const float W1 = 1.0f / 2048.0f;
    float s0 = ((a0.x + a1.x) + (a2.x + a3.x)) + W1 * ((b0.x + b1.x) + (b2.x + b3.x));
    float s1 = ((a0.y + a1.y) + (a2.y + a3.y)) + W1 * ((b0.y + b1.y) + (b2.y + b3.y));
    float s2 = ((a0.z + a1.z) + (a2.z + a3.z)) + W1 * ((b0.z + b1.z) + (b2.z + b3.z));
    float s3 = ((a0.w + a1.w) + (a2.w + a3.w)) + W1 * ((b0.w + b1.w) + (b2.w + b3.w));
    __half q0 = __float2half_rn(s0), q1 = __float2half_rn(s1);
    __half q2 = __float2half_rn(s2), q3 = __float2half_rn(s3);
    float f0 = __half2float(q0), f1 = __half2float(q1);
    float f2 = __half2float(q2), f3 = __half2float(q3);
    reinterpret_cast<ushort4*>(h16)[i] = make_ushort4(
        __half_as_ushort(q0), __half_as_ushort(q1),
        __half_as_ushort(q2), __half_as_ushort(q3));
    reinterpret_cast<uint32_t*>(h8)[i] = pack4_e4m3(f0 * 0.25f, f1 * 0.25f, f2 * 0.25f, f3 * 0.25f);
    reinterpret_cast<uint32_t*>(l8)[i] = pack4_e4m3((s0 - f0) * 512.f, (s1 - f1) * 512.f,
                                                    (s2 - f2) * 512.f, (s3 - f3) * 512.f);
}

// ---------------------------------------------- out = SUM(C) + 2^-9 SUM(D)
__global__ void reduce2_kernel(const float* __restrict__ pc, const float* __restrict__ pd,
                               float* __restrict__ out) {
    const size_t i = (size_t)blockIdx.x * 256 + threadIdx.x;
    const size_t off = (size_t)OUT_D * N_SAMP / 4;
    const float4* cv = reinterpret_cast<const float4*>(pc);
    const float4* dv = reinterpret_cast<const float4*>(pd);
    float4 c0 = cv[i], c1 = cv[i + off];
    float4 d0 = dv[i], d1 = dv[i + off];
    const float W2 = 1.0f / 512.0f;
    reinterpret_cast<float4*>(out)[i] = make_float4(
        (c0.x + c1.x) + W2 * (d0.x + d1.x),
        (c0.y + c1.y) + W2 * (d0.y + d1.y),
        (c0.z + c1.z) + W2 * (d0.z + d1.z),
        (c0.w + c1.w) + W2 * (d0.w + d1.w));
}

// ---------------------------------------------------------------- launch
extern "C" void kernel_launch(void* const* d_in, const int* in_sizes, int n_in,
                              void* d_out, int out_size) {
    (void)n_in; (void)out_size;

    const float* x;
    const float* Psi;
    if (in_sizes[0] == D_FEAT * N_SAMP) {
        x   = (const float*)d_in[0];
        Psi = (const float*)d_in[1];
    } else {
        x   = (const float*)d_in[1];
        Psi = (const float*)d_in[0];
    }
    float* out = (float*)d_out;

    __half *psi_h16, *x_h16, *xt_h16, *tmp_h16;
    unsigned char *psi_h8, *psi_l8, *x_h8, *x_l8, *xt_h8, *xt_l8, *tmp_h8, *tmp_l8;
    float *partA, *partB, *partC, *partD;
    cudaGetSymbolAddress((void**)&psi_h16, g_psi_h16);
    cudaGetSymbolAddress((void**)&psi_h8,  g_psi_h8);
    cudaGetSymbolAddress((void**)&psi_l8,  g_psi_l8);
    cudaGetSymbolAddress((void**)&x_h16,   g_x_h16);
    cudaGetSymbolAddress((void**)&x_h8,    g_x_h8);
    cudaGetSymbolAddress((void**)&x_l8,    g_x_l8);
    cudaGetSymbolAddress((void**)&xt_h16,  g_xt_h16);
    cudaGetSymbolAddress((void**)&xt_h8,   g_xt_h8);
    cudaGetSymbolAddress((void**)&xt_l8,   g_xt_l8);
    cudaGetSymbolAddress((void**)&tmp_h16, g_tmp_h16);
    cudaGetSymbolAddress((void**)&tmp_h8,  g_tmp_h8);
    cudaGetSymbolAddress((void**)&tmp_l8,  g_tmp_l8);
    cudaGetSymbolAddress((void**)&partA,   g_partA);
    cudaGetSymbolAddress((void**)&partB,   g_partB);
    cudaGetSymbolAddress((void**)&partC,   g_partC);
    cudaGetSymbolAddress((void**)&partD,   g_partD);

    const int SMEM_BYTES = 3 * STG_BYTES;   // 98304
    cudaFuncSetAttribute(gemm_hh, cudaFuncAttributeMaxDynamicSharedMemorySize, SMEM_BYTES);
    cudaFuncSetAttribute(gemm_x8, cudaFuncAttributeMaxDynamicSharedMemorySize, SMEM_BYTES);

    // 1) prep
    prep_psi_kernel<<<OUT_D, 256>>>(Psi, psi_h16, psi_h8, psi_l8);
    {
        dim3 grid(N_SAMP / 32, D_FEAT / 32);
        prep_x_kernel<<<grid, dim3(32, 8)>>>(x, x_h16, x_h8, x_l8, xt_h16, xt_h8, xt_l8);
    }

    // 2) GEMM1 (M=2048, N=4096, K=8192), split-K4
    {
        dim3 grid(OUT_D / 128, D_FEAT / 128, 4);
        gemm_hh<<<grid, 256, SMEM_BYTES>>>(psi_h16, x_h16, partA, D_FEAT, N_SAMP, N_SAMP / 4);
        gemm_x8<<<grid, 256, SMEM_BYTES>>>(psi_h8, psi_l8, x_h8, x_l8, partB, D_FEAT, N_SAMP, N_SAMP / 4);
    }
    reduce4_kernel<<<(OUT_D * D_FEAT / 4) / 256, 256>>>(partA, partB, tmp_h16, tmp_h8, tmp_l8);

    // 3) GEMM2 (M=2048, N=8192, K=4096), split-K2, B = x^T (materialized)
    {
        dim3 grid(OUT_D / 128, N_SAMP / 128, 2);
        gemm_hh<<<grid, 256, SMEM_BYTES>>>(tmp_h16, xt_h16, partC, N_SAMP, D_FEAT, D_FEAT / 2);
        gemm_x8<<<grid, 256, SMEM_BYTES>>>(tmp_h8, tmp_l8, xt_h8, xt_l8, partD, N_SAMP, D_FEAT, D_FEAT / 2);
    }
    reduce2_kernel<<<(OUT_D * N_SAMP / 4) / 256, 256>>>(partC, partD, out);
}

// round 9
// speedup vs baseline: 1.4160x; 1.4160x over previous
#include <cuda_runtime.h>
#include <cuda_bf16.h>
#include <cstdint>

// ---------------------------------------------------------------- shapes
#define D_FEAT 4096
#define N_SAMP 8192
#define OUT_D  2048

// ---------------------------------------------------------------- scratch
__device__ __nv_bfloat16 g_psi_hi[(size_t)OUT_D * N_SAMP];
__device__ __nv_bfloat16 g_psi_lo[(size_t)OUT_D * N_SAMP];
__device__ __nv_bfloat16 g_x_hi[(size_t)D_FEAT * N_SAMP];
__device__ __nv_bfloat16 g_x_lo[(size_t)D_FEAT * N_SAMP];
__device__ __nv_bfloat16 g_tmp_hi[(size_t)OUT_D * D_FEAT];
__device__ __nv_bfloat16 g_tmp_lo[(size_t)OUT_D * D_FEAT];
__device__ float g_part1[(size_t)4 * OUT_D * D_FEAT];
__device__ float g_part2[(size_t)2 * OUT_D * N_SAMP];

// ---------------------------------------------------------------- helpers
__device__ __forceinline__ uint32_t smem_u32(const void* p) {
    uint32_t a;
    asm("{ .reg .u64 t; cvta.to.shared.u64 t, %1; cvt.u32.u64 %0, t; }" : "=r"(a) : "l"(p));
    return a;
}
__device__ __forceinline__ void cpasync16(uint32_t s, const void* g) {
    asm volatile("cp.async.cg.shared.global [%0], [%1], 16;" :: "r"(s), "l"(g));
}
__device__ __forceinline__ void cp_commit() {
    asm volatile("cp.async.commit_group;" ::: "memory");
}
__device__ __forceinline__ void cp_wait1() {
    asm volatile("cp.async.wait_group 1;" ::: "memory");
}
__device__ __forceinline__ void ldsm4(uint32_t* r, uint32_t addr) {
    asm volatile("ldmatrix.sync.aligned.m8n8.x4.shared.b16 {%0,%1,%2,%3}, [%4];"
                 : "=r"(r[0]), "=r"(r[1]), "=r"(r[2]), "=r"(r[3]) : "r"(addr));
}
__device__ __forceinline__ void ldsm4t(uint32_t* r, uint32_t addr) {
    asm volatile("ldmatrix.sync.aligned.m8n8.x4.trans.shared.b16 {%0,%1,%2,%3}, [%4];"
                 : "=r"(r[0]), "=r"(r[1]), "=r"(r[2]), "=r"(r[3]) : "r"(addr));
}
__device__ __forceinline__ void mma16816(float* c, const uint32_t* a, const uint32_t* b) {
    asm volatile("mma.sync.aligned.m16n8k16.row.col.f32.bf16.bf16.f32 "
                 "{%0,%1,%2,%3}, {%4,%5,%6,%7}, {%8,%9}, {%0,%1,%2,%3};"
                 : "+f"(c[0]), "+f"(c[1]), "+f"(c[2]), "+f"(c[3])
                 : "r"(a[0]), "r"(a[1]), "r"(a[2]), "r"(a[3]), "r"(b[0]), "r"(b[1]));
}
__device__ __forceinline__ void split_f32(float v, __nv_bfloat16& h, __nv_bfloat16& l) {
    h = __float2bfloat16(v);
    l = __float2bfloat16(v - __bfloat162float(h));
}
__device__ __forceinline__ uint32_t sw64(uint32_t off) {
    return off ^ ((off >> 3) & 0x30);
}
__device__ __forceinline__ uint32_t sw128(uint32_t off) {
    return off ^ ((off >> 3) & 0x70);
}

// ------------------------------------------------- fused prep
#define XCHUNKS ((D_FEAT * (N_SAMP / 4)) / 256)

__global__ void prep_kernel(const float* __restrict__ Psi, const float* __restrict__ x,
                            __nv_bfloat16* __restrict__ phi, __nv_bfloat16* __restrict__ plo,
                            __nv_bfloat16* __restrict__ xh, __nv_bfloat16* __restrict__ xl) {
    if (blockIdx.x < OUT_D) {
        const int row = blockIdx.x;
        const float4* p = reinterpret_cast<const float4*>(Psi) + (size_t)row * (N_SAMP / 4);
        float4 v[8];
        float s = 0.f;
        #pragma unroll
        for (int q = 0; q < 8; ++q) {
            v[q] = p[q * 256 + threadIdx.x];
            s += (v[q].x + v[q].y) + (v[q].z + v[q].w);
        }
        __shared__ float red[256];
        red[threadIdx.x] = s;
        __syncthreads();
        #pragma unroll
        for (int off = 128; off > 0; off >>= 1) {
            if (threadIdx.x < off) red[threadIdx.x] += red[threadIdx.x + off];
            __syncthreads();
        }
        const float m = red[0] * (1.0f / N_SAMP);
        ushort4* hp = reinterpret_cast<ushort4*>(phi) + (size_t)row * (N_SAMP / 4);
        ushort4* lp = reinterpret_cast<ushort4*>(plo) + (size_t)row * (N_SAMP / 4);
        #pragma unroll
        for (int q = 0; q < 8; ++q) {
            float4 w = v[q];
            w.x -= m; w.y -= m; w.z -= m; w.w -= m;
            __nv_bfloat16 h0, l0, h1, l1, h2, l2, h3, l3;
            split_f32(w.x, h0, l0); split_f32(w.y, h1, l1);
            split_f32(w.z, h2, l2); split_f32(w.w, h3, l3);
            hp[q * 256 + threadIdx.x] = make_ushort4(
                __bfloat16_as_ushort(h0), __bfloat16_as_ushort(h1),
                __bfloat16_as_ushort(h2), __bfloat16_as_ushort(h3));
            lp[q * 256 + threadIdx.x] = make_ushort4(
                __bfloat16_as_ushort(l0), __bfloat16_as_ushort(l1),
                __bfloat16_as_ushort(l2), __bfloat16_as_ushort(l3));
        }
    } else {
        const size_t i = (size_t)(blockIdx.x - OUT_D) * 256 + threadIdx.x;
        float4 v = reinterpret_cast<const float4*>(x)[i];
        __nv_bfloat16 h0, l0, h1, l1, h2, l2, h3, l3;
        split_f32(v.x, h0, l0); split_f32(v.y, h1, l1);
        split_f32(v.z, h2, l2); split_f32(v.w, h3, l3);
        reinterpret_cast<ushort4*>(xh)[i] = make_ushort4(
            __bfloat16_as_ushort(h0), __bfloat16_as_ushort(h1),
            __bfloat16_as_ushort(h2), __bfloat16_as_ushort(h3));
        reinterpret_cast<ushort4*>(xl)[i] = make_ushort4(
            __bfloat16_as_ushort(l0), __bfloat16_as_ushort(l1),
            __bfloat16_as_ushort(l2), __bfloat16_as_ushort(l3));
    }
}

// ---------------------------------------------------------------- HMMA GEMM (split-K)
#define STG_BYTES 32768
#define AH_OFF 0
#define AL_OFF 8192
#define BH_OFF 16384
#define BL_OFF 24576

template <int BTRANS>
__global__ void __launch_bounds__(256, 2)
gemm_hmma(const __nv_bfloat16* __restrict__ Ahi, const __nv_bfloat16* __restrict__ Alo,
          const __nv_bfloat16* __restrict__ Bhi, const __nv_bfloat16* __restrict__ Blo,
          float* __restrict__ Cpart,
          int N, int K, int klen, int ldb) {
    extern __shared__ char smem[];
    const uint32_t sb = smem_u32(smem);

    const int tid  = threadIdx.x;
    const int wid  = tid >> 5;
    const int lane = tid & 31;
    const int wm   = wid & 3;
    const int wn   = wid >> 2;
    const int m0   = blockIdx.x * 128;
    const int n0   = blockIdx.y * 128;
    const int kz   = blockIdx.z * klen;
    float* C = Cpart + (size_t)blockIdx.z * ((size_t)gridDim.x * 128) * N;

    uint32_t soffA[2], soffB[2];
    size_t gA[2], gB[2];
    #pragma unroll
    for (int q = 0; q < 2; ++q) {
        const int id = q * 256 + tid;
        {
            const int r = id >> 2, sg = id & 3;
            soffA[q] = sw64((uint32_t)(r * 64 + sg * 16));
            gA[q]    = (size_t)(m0 + r) * K + kz + sg * 8;
        }
        if (BTRANS == 0) {
            const int r = id >> 2, sg = id & 3;
            soffB[q] = sw64((uint32_t)(r * 64 + sg * 16));
            gB[q]    = (size_t)(n0 + r) * (size_t)ldb + kz + sg * 8;
        } else {
            const int r = id >> 4, c = id & 15;
            const int sub = c >> 3;
            soffB[q] = sub * 4096 + sw128((uint32_t)(r * 128 + (c & 7) * 16));
            gB[q]    = (size_t)(kz + r) * (size_t)ldb + n0 + c * 8;
        }
    }

    auto load_stage = [&](int t) {
        const uint32_t base = sb + (t % 3) * STG_BYTES;
        const size_t ka = (size_t)t * 32;
        const size_t kb = BTRANS ? (size_t)t * 32 * (size_t)ldb : (size_t)t * 32;
        #pragma unroll
        for (int q = 0; q < 2; ++q) {
            cpasync16(base + AH_OFF + soffA[q], Ahi + gA[q] + ka);
            cpasync16(base + AL_OFF + soffA[q], Alo + gA[q] + ka);
            cpasync16(base + BH_OFF + soffB[q], Bhi + gB[q] + kb);
            cpasync16(base + BL_OFF + soffB[q], Blo + gB[q] + kb);
        }
        cp_commit();
    };

    const int quad = lane >> 3, l8 = lane & 7;
    const int a_row  = wm * 32 + (quad & 1) * 8 + l8;
    const int a_colq = (quad >> 1) * 8;
    const int b_row0 = wn * 64 + (quad >> 1) * 8 + l8;
    const int b_col0 = (quad & 1) * 8;
    const int b_kq   = (quad & 1) * 8 + l8;
    const int b_nq   = wn * 64 + (quad >> 1) * 8;

    float acc[2][8][4];
    #pragma unroll
    for (int i = 0; i < 2; ++i)
        #pragma unroll
        for (int j = 0; j < 8; ++j)
            #pragma unroll
            for (int e = 0; e < 4; ++e) acc[i][j][e] = 0.f;

    const int ntiles = klen / 32;
    load_stage(0);
    load_stage(1);

    for (int s = 0; s < ntiles; ++s) {
        cp_wait1();
        __syncthreads();
        if (s + 2 < ntiles) load_stage(s + 2);

        const uint32_t st = sb + (s % 3) * STG_BYTES;
        #pragma unroll
        for (int h = 0; h < 2; ++h) {
            const int k0 = h * 16;
            uint32_t Ah[2][4], Al[2][4];
            #pragma unroll
            for (int i = 0; i < 2; ++i) {
                const uint32_t ao = sw64((uint32_t)((a_row + i * 16) * 64 + (k0 + a_colq) * 2));
                ldsm4(Ah[i], st + AH_OFF + ao);
                ldsm4(Al[i], st + AL_OFF + ao);
            }
            #pragma unroll
            for (int jj = 0; jj < 2; ++jj) {
                uint32_t Bh[2][4], Bl[2][4];
                #pragma unroll
                for (int j = 0; j < 2; ++j) {
                    uint32_t bo;
                    if (BTRANS == 0) {
                        bo = sw64((uint32_t)((b_row0 + (jj * 2 + j) * 16) * 64 + (k0 + b_col0) * 2));
                        ldsm4(Bh[j], st + BH_OFF + bo);
                        ldsm4(Bl[j], st + BL_OFF + bo);
                    } else {
                        const int ncol = b_nq + (jj * 2 + j) * 16;
                        const int sub  = ncol >> 6;
                        bo = sub * 4096 + sw128((uint32_t)((k0 + b_kq) * 128 + (ncol & 63) * 2));
                        ldsm4t(Bh[j], st + BH_OFF + bo);
                        ldsm4t(Bl[j], st + BL_OFF + bo);
                    }
                }
                #pragma unroll
                for (int i = 0; i < 2; ++i)
                    #pragma unroll
                    for (int j = 0; j < 4; ++j) {
                        float* c = acc[i][jj * 4 + j];
                        const uint32_t* bh = &Bh[j >> 1][(j & 1) * 2];
                        const uint32_t* bl = &Bl[j >> 1][(j & 1) * 2];
                        mma16816(c, Ah[i], bh);
                        mma16816(c, Ah[i], bl);
                        mma16816(c, Al[i], bh);
                    }
            }
        }
    }

    const int r_base = m0 + wm * 32 + (lane >> 2);
    const int c_base = n0 + wn * 64 + (lane & 3) * 2;
    #pragma unroll
    for (int i = 0; i < 2; ++i) {
        #pragma unroll
        for (int j = 0; j < 8; ++j) {
            const int r0 = r_base + i * 16;
            const int c  = c_base + j * 8;
            *reinterpret_cast<float2*>(C + (size_t)r0 * N + c) =
                make_float2(acc[i][j][0], acc[i][j][1]);
            *reinterpret_cast<float2*>(C + (size_t)(r0 + 8) * N + c) =
                make_float2(acc[i][j][2], acc[i][j][3]);
        }
    }
}

// ---------------------------------------------- reduce 4 partials -> bf16 hi/lo
__global__ void reduce4_split_kernel(const float* __restrict__ p,
                                     __nv_bfloat16* __restrict__ hi,
                                     __nv_bfloat16* __restrict__ lo) {
    const size_t i = (size_t)blockIdx.x * 256 + threadIdx.x;
    const size_t off = (size_t)OUT_D * D_FEAT / 4;
    const float4* pv = reinterpret_cast<const float4*>(p);
    float4 a = pv[i], b = pv[i + off], c = pv[i + 2 * off], d = pv[i + 3 * off];
    float4 s = make_float4((a.x + b.x) + (c.x + d.x), (a.y + b.y) + (c.y + d.y),
                           (a.z + b.z) + (c.z + d.z), (a.w + b.w) + (c.w + d.w));
    __nv_bfloat16 h0, l0, h1, l1, h2, l2, h3, l3;
    split_f32(s.x, h0, l0); split_f32(s.y, h1, l1);
    split_f32(s.z, h2, l2); split_f32(s.w, h3, l3);
    reinterpret_cast<ushort4*>(hi)[i] = make_ushort4(
        __bfloat16_as_ushort(h0), __bfloat16_as_ushort(h1),
        __bfloat16_as_ushort(h2), __bfloat16_as_ushort(h3));
    reinterpret_cast<ushort4*>(lo)[i] = make_ushort4(
        __bfloat16_as_ushort(l0), __bfloat16_as_ushort(l1),
        __bfloat16_as_ushort(l2), __bfloat16_as_ushort(l3));
}

// ---------------------------------------------- reduce 2 partials -> fp32 out
__global__ void reduce2_kernel(const float* __restrict__ p, float* __restrict__ out) {
    const size_t i = (size_t)blockIdx.x * 256 + threadIdx.x;
    const size_t off = (size_t)OUT_D * N_SAMP / 4;
    const float4* pv = reinterpret_cast<const float4*>(p);
    float4 a = pv[i], b = pv[i + off];
    reinterpret_cast<float4*>(out)[i] = make_float4(a.x + b.x, a.y + b.y, a.z + b.z, a.w + b.w);
}

// ---------------------------------------------------------------- launch
extern "C" void kernel_launch(void* const* d_in, const int* in_sizes, int n_in,
                              void* d_out, int out_size) {
    (void)n_in; (void)out_size;

    const float* x;
    const float* Psi;
    if (in_sizes[0] == D_FEAT * N_SAMP) {
        x   = (const float*)d_in[0];
        Psi = (const float*)d_in[1];
    } else {
        x   = (const float*)d_in[1];
        Psi = (const float*)d_in[0];
    }
    float* out = (float*)d_out;

    __nv_bfloat16 *psi_hi, *psi_lo, *x_hi, *x_lo, *tmp_hi, *tmp_lo;
    float *part1, *part2;
    cudaGetSymbolAddress((void**)&psi_hi, g_psi_hi);
    cudaGetSymbolAddress((void**)&psi_lo, g_psi_lo);
    cudaGetSymbolAddress((void**)&x_hi,   g_x_hi);
    cudaGetSymbolAddress((void**)&x_lo,   g_x_lo);
    cudaGetSymbolAddress((void**)&tmp_hi, g_tmp_hi);
    cudaGetSymbolAddress((void**)&tmp_lo, g_tmp_lo);
    cudaGetSymbolAddress((void**)&part1,  g_part1);
    cudaGetSymbolAddress((void**)&part2,  g_part2);

    const int SMEM_BYTES = 3 * STG_BYTES;   // 98304
    cudaFuncSetAttribute(gemm_hmma<0>, cudaFuncAttributeMaxDynamicSharedMemorySize, SMEM_BYTES);
    cudaFuncSetAttribute(gemm_hmma<1>, cudaFuncAttributeMaxDynamicSharedMemorySize, SMEM_BYTES);

    // 1) fused prep
    prep_kernel<<<OUT_D + XCHUNKS, 256>>>(Psi, x, psi_hi, psi_lo, x_hi, x_lo);

    // 2) GEMM1 split-K4 (B = x, non-trans)
    {
        dim3 grid(OUT_D / 128, D_FEAT / 128, 4);
        gemm_hmma<0><<<grid, 256, SMEM_BYTES>>>(
            psi_hi, psi_lo, x_hi, x_lo, part1, D_FEAT, N_SAMP, N_SAMP / 4, N_SAMP);
    }
    reduce4_split_kernel<<<(OUT_D * D_FEAT / 4) / 256, 256>>>(part1, tmp_hi, tmp_lo);

    // 3) GEMM2 split-K2 (B = x in [d,n] layout, trans ldsm)
    {
        dim3 grid(OUT_D / 128, N_SAMP / 128, 2);
        gemm_hmma<1><<<grid, 256, SMEM_BYTES>>>(
            tmp_hi, tmp_lo, x_hi, x_lo, part2, N_SAMP, D_FEAT, D_FEAT / 2, N_SAMP);
    }
    reduce2_kernel<<<(OUT_D * N_SAMP / 4) / 256, 256>>>(part2, out);
}

// round 10
// speedup vs baseline: 2.0035x; 1.4149x over previous
#include <cuda_runtime.h>
#include <cuda_fp16.h>
#include <cstdint>

// ---------------------------------------------------------------- shapes
#define D_FEAT 4096
#define N_SAMP 8192
#define OUT_D  2048

// ---------------------------------------------------------------- scratch
__device__ __half g_psi_h[(size_t)OUT_D * N_SAMP];
__device__ __half g_x_h[(size_t)D_FEAT * N_SAMP];
__device__ __half g_x_l[(size_t)D_FEAT * N_SAMP];
__device__ __half g_tmp_h[(size_t)OUT_D * D_FEAT];
__device__ float g_part1[(size_t)4 * OUT_D * D_FEAT];
__device__ float g_part2[(size_t)2 * OUT_D * N_SAMP];

// ---------------------------------------------------------------- helpers
__device__ __forceinline__ uint32_t smem_u32(const void* p) {
    uint32_t a;
    asm("{ .reg .u64 t; cvta.to.shared.u64 t, %1; cvt.u32.u64 %0, t; }" : "=r"(a) : "l"(p));
    return a;
}
__device__ __forceinline__ void cpasync16(uint32_t s, const void* g) {
    asm volatile("cp.async.cg.shared.global [%0], [%1], 16;" :: "r"(s), "l"(g));
}
__device__ __forceinline__ void cp_commit() {
    asm volatile("cp.async.commit_group;" ::: "memory");
}
__device__ __forceinline__ void cp_wait1() {
    asm volatile("cp.async.wait_group 1;" ::: "memory");
}
__device__ __forceinline__ void ldsm4(uint32_t* r, uint32_t addr) {
    asm volatile("ldmatrix.sync.aligned.m8n8.x4.shared.b16 {%0,%1,%2,%3}, [%4];"
                 : "=r"(r[0]), "=r"(r[1]), "=r"(r[2]), "=r"(r[3]) : "r"(addr));
}
__device__ __forceinline__ void ldsm4t(uint32_t* r, uint32_t addr) {
    asm volatile("ldmatrix.sync.aligned.m8n8.x4.trans.shared.b16 {%0,%1,%2,%3}, [%4];"
                 : "=r"(r[0]), "=r"(r[1]), "=r"(r[2]), "=r"(r[3]) : "r"(addr));
}
__device__ __forceinline__ void mma_f16(float* c, const uint32_t* a, const uint32_t* b) {
    asm volatile("mma.sync.aligned.m16n8k16.row.col.f32.f16.f16.f32 "
                 "{%0,%1,%2,%3}, {%4,%5,%6,%7}, {%8,%9}, {%0,%1,%2,%3};"
                 : "+f"(c[0]), "+f"(c[1]), "+f"(c[2]), "+f"(c[3])
                 : "r"(a[0]), "r"(a[1]), "r"(a[2]), "r"(a[3]), "r"(b[0]), "r"(b[1]));
}
__device__ __forceinline__ uint32_t sw64(uint32_t off) {
    return off ^ ((off >> 3) & 0x30);
}
__device__ __forceinline__ uint32_t sw128(uint32_t off) {
    return off ^ ((off >> 3) & 0x70);
}

// ------------------------------------------------- fused prep
// blocks [0, OUT_D): Psi row mean+center -> fp16 h (A side: hi only)
// blocks [OUT_D, OUT_D + XCHUNKS): x -> fp16 h + fp16 l (B side: both)
#define XCHUNKS ((D_FEAT * (N_SAMP / 4)) / 256)

__global__ void prep_kernel(const float* __restrict__ Psi, const float* __restrict__ x,
                            __half* __restrict__ ph,
                            __half* __restrict__ xh, __half* __restrict__ xl) {
    if (blockIdx.x < OUT_D) {
        const int row = blockIdx.x;
        const float4* p = reinterpret_cast<const float4*>(Psi) + (size_t)row * (N_SAMP / 4);
        float4 v[8];
        float s = 0.f;
        #pragma unroll
        for (int q = 0; q < 8; ++q) {
            v[q] = p[q * 256 + threadIdx.x];
            s += (v[q].x + v[q].y) + (v[q].z + v[q].w);
        }
        __shared__ float red[256];
        red[threadIdx.x] = s;
        __syncthreads();
        #pragma unroll
        for (int off = 128; off > 0; off >>= 1) {
            if (threadIdx.x < off) red[threadIdx.x] += red[threadIdx.x + off];
            __syncthreads();
        }
        const float m = red[0] * (1.0f / N_SAMP);
        ushort4* hp = reinterpret_cast<ushort4*>(ph) + (size_t)row * (N_SAMP / 4);
        #pragma unroll
        for (int q = 0; q < 8; ++q) {
            float4 w = v[q];
            __half h0 = __float2half_rn(w.x - m);
            __half h1 = __float2half_rn(w.y - m);
            __half h2 = __float2half_rn(w.z - m);
            __half h3 = __float2half_rn(w.w - m);
            hp[q * 256 + threadIdx.x] = make_ushort4(
                __half_as_ushort(h0), __half_as_ushort(h1),
                __half_as_ushort(h2), __half_as_ushort(h3));
        }
    } else {
        const size_t i = (size_t)(blockIdx.x - OUT_D) * 256 + threadIdx.x;
        float4 v = reinterpret_cast<const float4*>(x)[i];
        __half h0 = __float2half_rn(v.x), h1 = __float2half_rn(v.y);
        __half h2 = __float2half_rn(v.z), h3 = __float2half_rn(v.w);
        __half l0 = __float2half_rn(v.x - __half2float(h0));
        __half l1 = __float2half_rn(v.y - __half2float(h1));
        __half l2 = __float2half_rn(v.z - __half2float(h2));
        __half l3 = __float2half_rn(v.w - __half2float(h3));
        reinterpret_cast<ushort4*>(xh)[i] = make_ushort4(
            __half_as_ushort(h0), __half_as_ushort(h1),
            __half_as_ushort(h2), __half_as_ushort(h3));
        reinterpret_cast<ushort4*>(xl)[i] = make_ushort4(
            __half_as_ushort(l0), __half_as_ushort(l1),
            __half_as_ushort(l2), __half_as_ushort(l3));
    }
}

// ---------------------------------------------------------------- fp16 2-term GEMM (split-K)
// Cpart[z][M,N] = Ah[M,kz:kz+klen] * (Bh+Bl)[N-slab]^T  (== Ah * B exactly)
// BTRANS=0: B arrays [N, K] K-contiguous (non-trans ldsm, SW64 64B rows).
// BTRANS=1: B arrays [K, ldb] N-contiguous (trans ldsm, two SW128 64-col subtiles).
// CTA 128x128, 256 threads (8 warps, warp tile 32x64), K_TILE=32,
// 3-stage cp.async ring (72KB), 2 CTAs/SM. fp32 partial stores.
#define STG_BYTES 24576
#define A_OFF  0
#define BH_OFF 8192
#define BL_OFF 16384

template <int BTRANS>
__global__ void __launch_bounds__(256, 2)
gemm_f16x2(const __half* __restrict__ Ah,
           const __half* __restrict__ Bh, const __half* __restrict__ Bl,
           float* __restrict__ Cpart,
           int N, int K, int klen, int ldb) {
    extern __shared__ char smem[];
    const uint32_t sb = smem_u32(smem);

    const int tid  = threadIdx.x;
    const int wid  = tid >> 5;
    const int lane = tid & 31;
    const int wm   = wid & 3;
    const int wn   = wid >> 2;
    const int m0   = blockIdx.x * 128;
    const int n0   = blockIdx.y * 128;
    const int kz   = blockIdx.z * klen;
    float* C = Cpart + (size_t)blockIdx.z * ((size_t)gridDim.x * 128) * N;

    uint32_t soffA[2], soffB[2];
    size_t gA[2], gB[2];
    #pragma unroll
    for (int q = 0; q < 2; ++q) {
        const int id = q * 256 + tid;
        {
            const int r = id >> 2, sg = id & 3;
            soffA[q] = sw64((uint32_t)(r * 64 + sg * 16));
            gA[q]    = (size_t)(m0 + r) * K + kz + sg * 8;
        }
        if (BTRANS == 0) {
            const int r = id >> 2, sg = id & 3;
            soffB[q] = sw64((uint32_t)(r * 64 + sg * 16));
            gB[q]    = (size_t)(n0 + r) * (size_t)ldb + kz + sg * 8;
        } else {
            const int r = id >> 4, c = id & 15;
            const int sub = c >> 3;
            soffB[q] = sub * 4096 + sw128((uint32_t)(r * 128 + (c & 7) * 16));
            gB[q]    = (size_t)(kz + r) * (size_t)ldb + n0 + c * 8;
        }
    }

    auto load_stage = [&](int t) {
        const uint32_t base = sb + (t % 3) * STG_BYTES;
        const size_t ka = (size_t)t * 32;
        const size_t kb = BTRANS ? (size_t)t * 32 * (size_t)ldb : (size_t)t * 32;
        #pragma unroll
        for (int q = 0; q < 2; ++q) {
            cpasync16(base + A_OFF  + soffA[q], Ah + gA[q] + ka);
            cpasync16(base + BH_OFF + soffB[q], Bh + gB[q] + kb);
            cpasync16(base + BL_OFF + soffB[q], Bl + gB[q] + kb);
        }
        cp_commit();
    };

    const int quad = lane >> 3, l8 = lane & 7;
    const int a_row  = wm * 32 + (quad & 1) * 8 + l8;
    const int a_colq = (quad >> 1) * 8;
    const int b_row0 = wn * 64 + (quad >> 1) * 8 + l8;
    const int b_col0 = (quad & 1) * 8;
    const int b_kq   = (quad & 1) * 8 + l8;
    const int b_nq   = wn * 64 + (quad >> 1) * 8;

    float acc[2][8][4];
    #pragma unroll
    for (int i = 0; i < 2; ++i)
        #pragma unroll
        for (int j = 0; j < 8; ++j)
            #pragma unroll
            for (int e = 0; e < 4; ++e) acc[i][j][e] = 0.f;

    const int ntiles = klen / 32;
    load_stage(0);
    load_stage(1);

    for (int s = 0; s < ntiles; ++s) {
        cp_wait1();
        __syncthreads();
        if (s + 2 < ntiles) load_stage(s + 2);

        const uint32_t st = sb + (s % 3) * STG_BYTES;
        #pragma unroll
        for (int h = 0; h < 2; ++h) {
            const int k0 = h * 16;
            uint32_t Af[2][4];
            #pragma unroll
            for (int i = 0; i < 2; ++i) {
                const uint32_t ao = sw64((uint32_t)((a_row + i * 16) * 64 + (k0 + a_colq) * 2));
                ldsm4(Af[i], st + A_OFF + ao);
            }
            #pragma unroll
            for (int jj = 0; jj < 2; ++jj) {
                uint32_t Bhf[2][4], Blf[2][4];
                #pragma unroll
                for (int j = 0; j < 2; ++j) {
                    uint32_t bo;
                    if (BTRANS == 0) {
                        bo = sw64((uint32_t)((b_row0 + (jj * 2 + j) * 16) * 64 + (k0 + b_col0) * 2));
                        ldsm4(Bhf[j], st + BH_OFF + bo);
                        ldsm4(Blf[j], st + BL_OFF + bo);
                    } else {
                        const int ncol = b_nq + (jj * 2 + j) * 16;
                        const int sub  = ncol >> 6;
                        bo = sub * 4096 + sw128((uint32_t)((k0 + b_kq) * 128 + (ncol & 63) * 2));
                        ldsm4t(Bhf[j], st + BH_OFF + bo);
                        ldsm4t(Blf[j], st + BL_OFF + bo);
                    }
                }
                #pragma unroll
                for (int i = 0; i < 2; ++i)
                    #pragma unroll
                    for (int j = 0; j < 4; ++j) {
                        float* c = acc[i][jj * 4 + j];
                        mma_f16(c, Af[i], &Bhf[j >> 1][(j & 1) * 2]);
                        mma_f16(c, Af[i], &Blf[j >> 1][(j & 1) * 2]);
                    }
            }
        }
    }

    const int r_base = m0 + wm * 32 + (lane >> 2);
    const int c_base = n0 + wn * 64 + (lane & 3) * 2;
    #pragma unroll
    for (int i = 0; i < 2; ++i) {
        #pragma unroll
        for (int j = 0; j < 8; ++j) {
            const int r0 = r_base + i * 16;
            const int c  = c_base + j * 8;
            *reinterpret_cast<float2*>(C + (size_t)r0 * N + c) =
                make_float2(acc[i][j][0], acc[i][j][1]);
            *reinterpret_cast<float2*>(C + (size_t)(r0 + 8) * N + c) =
                make_float2(acc[i][j][2], acc[i][j][3]);
        }
    }
}

// ---------------------------------------------- reduce 4 partials -> fp16 tmp
__global__ void reduce4_kernel(const float* __restrict__ p, __half* __restrict__ h16) {
    const size_t i = (size_t)blockIdx.x * 256 + threadIdx.x;
    const size_t off = (size_t)OUT_D * D_FEAT / 4;
    const float4* pv = reinterpret_cast<const float4*>(p);
    float4 a = pv[i], b = pv[i + off], c = pv[i + 2 * off], d = pv[i + 3 * off];
    __half h0 = __float2half_rn((a.x + b.x) + (c.x + d.x));
    __half h1 = __float2half_rn((a.y + b.y) + (c.y + d.y));
    __half h2 = __float2half_rn((a.z + b.z) + (c.z + d.z));
    __half h3 = __float2half_rn((a.w + b.w) + (c.w + d.w));
    reinterpret_cast<ushort4*>(h16)[i] = make_ushort4(
        __half_as_ushort(h0), __half_as_ushort(h1),
        __half_as_ushort(h2), __half_as_ushort(h3));
}

// ---------------------------------------------- reduce 2 partials -> fp32 out
__global__ void reduce2_kernel(const float* __restrict__ p, float* __restrict__ out) {
    const size_t i = (size_t)blockIdx.x * 256 + threadIdx.x;
    const size_t off = (size_t)OUT_D * N_SAMP / 4;
    const float4* pv = reinterpret_cast<const float4*>(p);
    float4 a = pv[i], b = pv[i + off];
    reinterpret_cast<float4*>(out)[i] = make_float4(a.x + b.x, a.y + b.y, a.z + b.z, a.w + b.w);
}

// ---------------------------------------------------------------- launch
extern "C" void kernel_launch(void* const* d_in, const int* in_sizes, int n_in,
                              void* d_out, int out_size) {
    (void)n_in; (void)out_size;

    const float* x;
    const float* Psi;
    if (in_sizes[0] == D_FEAT * N_SAMP) {
        x   = (const float*)d_in[0];
        Psi = (const float*)d_in[1];
    } else {
        x   = (const float*)d_in[1];
        Psi = (const float*)d_in[0];
    }
    float* out = (float*)d_out;

    __half *psi_h, *x_h, *x_l, *tmp_h;
    float *part1, *part2;
    cudaGetSymbolAddress((void**)&psi_h, g_psi_h);
    cudaGetSymbolAddress((void**)&x_h,   g_x_h);
    cudaGetSymbolAddress((void**)&x_l,   g_x_l);
    cudaGetSymbolAddress((void**)&tmp_h, g_tmp_h);
    cudaGetSymbolAddress((void**)&part1, g_part1);
    cudaGetSymbolAddress((void**)&part2, g_part2);

    const int SMEM_BYTES = 3 * STG_BYTES;   // 73728
    cudaFuncSetAttribute(gemm_f16x2<0>, cudaFuncAttributeMaxDynamicSharedMemorySize, SMEM_BYTES);
    cudaFuncSetAttribute(gemm_f16x2<1>, cudaFuncAttributeMaxDynamicSharedMemorySize, SMEM_BYTES);

    // 1) fused prep: Psi -> fp16 (centered), x -> fp16 hi + fp16 lo
    prep_kernel<<<OUT_D + XCHUNKS, 256>>>(Psi, x, psi_h, x_h, x_l);

    // 2) GEMM1 split-K4: part1[z] = psi_h . x  (B = x_h + x_l, non-trans)
    {
        dim3 grid(OUT_D / 128, D_FEAT / 128, 4);
        gemm_f16x2<0><<<grid, 256, SMEM_BYTES>>>(
            psi_h, x_h, x_l, part1, D_FEAT, N_SAMP, N_SAMP / 4, N_SAMP);
    }
    reduce4_kernel<<<(OUT_D * D_FEAT / 4) / 256, 256>>>(part1, tmp_h);

    // 3) GEMM2 split-K2: part2[z] = tmp_h . x  (B = x in [d,n] layout, trans ldsm)
    {
        dim3 grid(OUT_D / 128, N_SAMP / 128, 2);
        gemm_f16x2<1><<<grid, 256, SMEM_BYTES>>>(
            tmp_h, x_h, x_l, part2, N_SAMP, D_FEAT, D_FEAT / 2, N_SAMP);
    }
    reduce2_kernel<<<(OUT_D * N_SAMP / 4) / 256, 256>>>(part2, out);
}